// round 16
// baseline (speedup 1.0000x reference)
#include <cuda_runtime.h>
#include <cuda_bf16.h>
#include <math.h>
#include <stdint.h>

#define NN   8192
#define EE   262144
#define DIN  512
#define H1D  256
#define LATD 128

// ---------------- scratch (device globals; no allocation allowed) ----------
__device__ int   g_is64;
__device__ int   g_cnt[NN];
__device__ int   g_off[NN + 1];
__device__ int   g_cur[NN];
__device__ int   g_bsum[32];
__device__ int   g_boff[32];
__device__ int   g_csr[EE];
__device__ float g_dis[NN];
__device__ float g_hs1[NN * H1D];
__device__ float g_hs2[NN * LATD];
__device__ __nv_bfloat16 g_xh [NN * DIN],  g_xl [NN * DIN];
__device__ __nv_bfloat16 g_z1h[NN * H1D],  g_z1l[NN * H1D];
__device__ __nv_bfloat16 g_z2h[NN * LATD], g_z2l[NN * LATD];
__device__ __nv_bfloat16 g_muh[NN * LATD], g_mul[NN * LATD];
__device__ __nv_bfloat16 g_w1h[H1D * DIN],  g_w1l[H1D * DIN];
__device__ __nv_bfloat16 g_w2h[LATD * H1D], g_w2l[LATD * H1D];
__device__ __nv_bfloat16 g_whh[2 * LATD * LATD], g_whl[2 * LATD * LATD];

// ---------------- split helpers ---------------------------------------------
__device__ __forceinline__ void split1(float v, __nv_bfloat16& h, __nv_bfloat16& l) {
    h = __float2bfloat16(v);
    l = __float2bfloat16(v - __bfloat162float(h));
}

__device__ __forceinline__ void split4(const float* src, int i,
                                       __nv_bfloat16* ph, __nv_bfloat16* pl) {
    float4 v = ((const float4*)src)[i];
    __nv_bfloat16 h0, h1, h2, h3, l0, l1, l2, l3;
    split1(v.x, h0, l0); split1(v.y, h1, l1); split1(v.z, h2, l2); split1(v.w, h3, l3);
    uint2 hv, lv;
    hv.x = ((uint32_t)__bfloat16_as_ushort(h1) << 16) | __bfloat16_as_ushort(h0);
    hv.y = ((uint32_t)__bfloat16_as_ushort(h3) << 16) | __bfloat16_as_ushort(h2);
    lv.x = ((uint32_t)__bfloat16_as_ushort(l1) << 16) | __bfloat16_as_ushort(l0);
    lv.y = ((uint32_t)__bfloat16_as_ushort(l3) << 16) | __bfloat16_as_ushort(l2);
    ((uint2*)ph)[i] = hv;
    ((uint2*)pl)[i] = lv;
}

__device__ __forceinline__ void wsplit1(const float* W, __nv_bfloat16* outh,
                                        __nv_bfloat16* outl, int Kdim, int Ndim, int idx) {
    int k = idx / Ndim, n = idx % Ndim;
    __nv_bfloat16 h, l;
    split1(W[idx], h, l);
    outh[(size_t)n * Kdim + k] = h;
    outl[(size_t)n * Kdim + k] = l;
}

// ---------------- launch 1 ----------------------------------------------------
__global__ void k_init() {
    int i = blockIdx.x * blockDim.x + threadIdx.x;
    if (i < NN) g_cnt[i] = 0;
    if (i == 0) g_is64 = 1;
}

// ---------------- launch 2: edge-width detect + all operand prep ------------
__global__ void k_detprep(const int* __restrict__ ei, const float* __restrict__ x,
                          const float* __restrict__ W1, const float* __restrict__ W2,
                          const float* __restrict__ Wmu, const float* __restrict__ Wlv) {
    int b = blockIdx.x, t = threadIdx.x;
    if (b < 32) {
        int i = b * 256 + t;
        if (ei[2 * i + 1] != 0) g_is64 = 0;
        return;
    }
    b -= 32;
    if (b < 4096) {
        split4(x, b * 256 + t, g_xh, g_xl);
    } else if (b < 4608) {
        wsplit1(W1, g_w1h, g_w1l, DIN, H1D, (b - 4096) * 256 + t);
    } else if (b < 4736) {
        wsplit1(W2, g_w2h, g_w2l, H1D, LATD, (b - 4608) * 256 + t);
    } else if (b < 4800) {
        wsplit1(Wmu, g_whh, g_whl, LATD, LATD, (b - 4736) * 256 + t);
    } else {
        wsplit1(Wlv, g_whh + LATD * LATD, g_whl + LATD * LATD, LATD, LATD,
                (b - 4800) * 256 + t);
    }
}

__device__ __forceinline__ int edge_val(const int* ei, int idx) {
    return g_is64 ? ei[2 * idx] : ei[idx];
}

// ---------------- launch 3: degree count ------------------------------------
__global__ void k_count(const int* __restrict__ ei) {
    int e = blockIdx.x * blockDim.x + threadIdx.x;
    if (e >= EE) return;
    int c = edge_val(ei, EE + e);
    atomicAdd(&g_cnt[c], 1);
}

// ---------------- hierarchical scan ------------------------------------------
__global__ void k_scan_a() {
    __shared__ int ws[8];
    int t = threadIdx.x, lane = t & 31, w = t >> 5;
    int i = blockIdx.x * 256 + t;
    int c = g_cnt[i];
    int v = c;
#pragma unroll
    for (int d = 1; d < 32; d <<= 1) {
        int u = __shfl_up_sync(0xffffffff, v, d);
        if (lane >= d) v += u;
    }
    if (lane == 31) ws[w] = v;
    __syncthreads();
    if (t < 8) {
        int x = ws[t];
#pragma unroll
        for (int d = 1; d < 8; d <<= 1) {
            int u = __shfl_up_sync(0xff, x, d);
            if (t >= d) x += u;
        }
        ws[t] = x;
    }
    __syncthreads();
    int excl = (w ? ws[w - 1] : 0) + v - c;
    g_off[i] = excl;
    g_dis[i] = rsqrtf((float)(c + 2));
    if (t == 255) g_bsum[blockIdx.x] = excl + c;
}

__global__ void k_scan_b() {
    int t = threadIdx.x;
    int c = g_bsum[t];
    int v = c;
#pragma unroll
    for (int d = 1; d < 32; d <<= 1) {
        int u = __shfl_up_sync(0xffffffff, v, d);
        if (t >= d) v += u;
    }
    g_boff[t] = v - c;
    if (t == 31) g_off[NN] = v;
}

__global__ void k_scan_c() {
    int i = blockIdx.x * 256 + threadIdx.x;
    int o = g_off[i] + g_boff[blockIdx.x];
    g_off[i] = o;
    g_cur[i] = o;
}

__global__ void k_fill(const int* __restrict__ ei) {
    int e = blockIdx.x * blockDim.x + threadIdx.x;
    if (e >= EE) return;
    int r = edge_val(ei, e);
    int c = edge_val(ei, EE + e);
    int p = atomicAdd(&g_cur[c], 1);
    g_csr[p] = r;
}

// ---------------- neighborhood aggregation ----------------------------------
__global__ void k_agg(const float* __restrict__ hs, const float* __restrict__ bias,
                      __nv_bfloat16* __restrict__ zh, __nv_bfloat16* __restrict__ zl,
                      int F, int relu)
{
    __shared__ int   sj[256];
    __shared__ float sd[256];
    int i = blockIdx.x;
    int f = threadIdx.x;
    float di = g_dis[i];
    float a0 = 2.f * di * hs[(size_t)i * F + f], a1 = 0.f, a2 = 0.f, a3 = 0.f;
    int s = g_off[i], e = g_off[i + 1];
    for (int base = s; base < e; base += blockDim.x) {
        int m = min((int)blockDim.x, e - base);
        __syncthreads();
        if (f < m) {
            int j = g_csr[base + f];
            sj[f] = j;
            sd[f] = g_dis[j];
        }
        __syncthreads();
        int p = 0;
        for (; p + 4 <= m; p += 4) {
            float v0 = hs[(size_t)sj[p + 0] * F + f];
            float v1 = hs[(size_t)sj[p + 1] * F + f];
            float v2 = hs[(size_t)sj[p + 2] * F + f];
            float v3 = hs[(size_t)sj[p + 3] * F + f];
            a0 = fmaf(sd[p + 0], v0, a0);
            a1 = fmaf(sd[p + 1], v1, a1);
            a2 = fmaf(sd[p + 2], v2, a2);
            a3 = fmaf(sd[p + 3], v3, a3);
        }
        for (; p < m; p++) a0 = fmaf(sd[p], hs[(size_t)sj[p] * F + f], a0);
    }
    float v = di * ((a0 + a1) + (a2 + a3)) + bias[f];
    if (relu) v = fmaxf(v, 0.f);
    __nv_bfloat16 h, l;
    split1(v, h, l);
    zh[(size_t)i * F + f] = h;
    zl[(size_t)i * F + f] = l;
}

// ---------------- mma.sync helpers ------------------------------------------
__device__ __forceinline__ uint32_t smem_u32(const void* p) {
    uint32_t a;
    asm("{ .reg .u64 t; cvta.to.shared.u64 t, %1; cvt.u32.u64 %0, t; }" : "=r"(a) : "l"(p));
    return a;
}

__device__ __forceinline__ void ldsm_x4(uint32_t* r, uint32_t addr) {
    asm volatile("ldmatrix.sync.aligned.m8n8.x4.shared.b16 {%0,%1,%2,%3}, [%4];"
                 : "=r"(r[0]), "=r"(r[1]), "=r"(r[2]), "=r"(r[3]) : "r"(addr));
}

__device__ __forceinline__ void mma16816(float* d, const uint32_t* a, const uint32_t* b) {
    asm volatile("mma.sync.aligned.m16n8k16.row.col.f32.bf16.bf16.f32 "
                 "{%0,%1,%2,%3}, {%4,%5,%6,%7}, {%8,%9}, {%0,%1,%2,%3};"
                 : "+f"(d[0]), "+f"(d[1]), "+f"(d[2]), "+f"(d[3])
                 : "r"(a[0]), "r"(a[1]), "r"(a[2]), "r"(a[3]), "r"(b[0]), "r"(b[1]));
}

__device__ __forceinline__ void cpa16(uint32_t saddr, const void* g) {
    asm volatile("cp.async.cg.shared.global [%0], [%1], 16;"
                 :: "r"(saddr), "l"(g) : "memory");
}
#define CP_COMMIT() asm volatile("cp.async.commit_group;" ::: "memory")
#define CP_WAIT0()  asm volatile("cp.async.wait_group 0;" ::: "memory")
#define CP_WAIT1()  asm volatile("cp.async.wait_group 1;" ::: "memory")

#define TP        136                     // adj tile pitch (bf16)
#define TP2       (TP * 2)
#define TILE_B    (128 * TP2)             // 34816
#define ADJ_SMEM  (3 * TILE_B)            // 104448 (occ 2)

#define SP        72                      // gemm sub-tile pitch (bf16), 144B rows
#define SPB       (SP * 2)
#define STILE_B   (128 * SPB)             // 18432 (128 rows x 64 cols)
#define STAGE_B   (4 * STILE_B)           // 73728
#define GEMM_SMEM (2 * STAGE_B)           // 147456 (occ 1)

// ---- adj warp pass: 32(m) x 64(n), 8 k-steps, pitch TP ----------------------
__device__ __forceinline__ void mma_pass_adj(uint32_t sA, uint32_t sB, int m_w, int n_w,
                                             float d[2][8][4], int lane) {
    uint32_t a_base = sA + ((m_w + (lane & 15)) * TP + (lane >> 4) * 8) * 2;
    int bmi = lane >> 3;
    uint32_t b_base = sB + ((n_w + ((bmi >> 1) * 8) + (lane & 7)) * TP + (bmi & 1) * 8) * 2;
#pragma unroll
    for (int kk = 0; kk < 8; kk++) {
        int k0 = kk * 16;
        uint32_t a[2][4];
        ldsm_x4(a[0], a_base + k0 * 2);
        ldsm_x4(a[1], a_base + (16 * TP + k0) * 2);
        uint32_t b[4][4];
#pragma unroll
        for (int np = 0; np < 4; np++)
            ldsm_x4(b[np], b_base + (np * 16 * TP + k0) * 2);
#pragma unroll
        for (int mi = 0; mi < 2; mi++)
#pragma unroll
            for (int np = 0; np < 4; np++) {
                mma16816(d[mi][np * 2 + 0], a[mi], &b[np][0]);
                mma16816(d[mi][np * 2 + 1], a[mi], &b[np][2]);
            }
    }
}

// ---- fused gemm k-loop: 32(m) x 64(n), 4 k-steps, all 3 split-passes --------
// fragments loaded ONCE per k-step (12 ldsm / 48 HMMA); HMMA issued in three
// full sweeps over all 16 accumulators so each accumulator's reuse distance is
// 16 instructions (covers HMMA latency) instead of 2.
__device__ __forceinline__ void mma_fused_g(uint32_t uAh, uint32_t uAl,
                                            uint32_t uBh, uint32_t uBl,
                                            int m_w, int n_w, float d[2][8][4], int lane) {
    uint32_t a_off = ((m_w + (lane & 15)) * SP + (lane >> 4) * 8) * 2;
    int bmi = lane >> 3;
    uint32_t b_off = ((n_w + ((bmi >> 1) * 8) + (lane & 7)) * SP + (bmi & 1) * 8) * 2;
#pragma unroll
    for (int kk = 0; kk < 4; kk++) {
        uint32_t k0 = kk * 32;            // 16 bf16 = 32 bytes
        uint32_t ah[2][4], al[2][4], bh[4][4], bl[4][4];
        ldsm_x4(ah[0], uAh + a_off + k0);
        ldsm_x4(ah[1], uAh + a_off + 16 * SPB + k0);
        ldsm_x4(al[0], uAl + a_off + k0);
        ldsm_x4(al[1], uAl + a_off + 16 * SPB + k0);
#pragma unroll
        for (int np = 0; np < 4; np++) {
            ldsm_x4(bh[np], uBh + b_off + np * 16 * SPB + k0);
            ldsm_x4(bl[np], uBl + b_off + np * 16 * SPB + k0);
        }
        // sweep 1: Ah x Bh over all 16 accumulators
#pragma unroll
        for (int mi = 0; mi < 2; mi++)
#pragma unroll
            for (int np = 0; np < 4; np++) {
                mma16816(d[mi][np * 2 + 0], ah[mi], &bh[np][0]);
                mma16816(d[mi][np * 2 + 1], ah[mi], &bh[np][2]);
            }
        // sweep 2: Ah x Bl
#pragma unroll
        for (int mi = 0; mi < 2; mi++)
#pragma unroll
            for (int np = 0; np < 4; np++) {
                mma16816(d[mi][np * 2 + 0], ah[mi], &bl[np][0]);
                mma16816(d[mi][np * 2 + 1], ah[mi], &bl[np][2]);
            }
        // sweep 3: Al x Bh
#pragma unroll
        for (int mi = 0; mi < 2; mi++)
#pragma unroll
            for (int np = 0; np < 4; np++) {
                mma16816(d[mi][np * 2 + 0], al[mi], &bh[np][0]);
                mma16816(d[mi][np * 2 + 1], al[mi], &bh[np][2]);
            }
    }
}

// cp.async 128-row x 64-col bf16 sub-tile (row length K, col offset kc)
__device__ __forceinline__ void load_sub(const __nv_bfloat16* g, int row0, int K,
                                         int kc, uint32_t dst) {
    int tid = threadIdx.x;
#pragma unroll
    for (int q = 0; q < 4; q++) {
        int idx = q * 256 + tid;          // 128 rows x 8 16B-chunks
        int r = idx >> 3, c = idx & 7;
        cpa16(dst + r * SPB + c * 16, g + (size_t)(row0 + r) * K + kc + c * 8);
    }
}

// cp.async 128x128 bf16 tile (contiguous rows, pitch TP) — adj
__device__ __forceinline__ void load_tile_cpa(const __nv_bfloat16* g, int rowblk,
                                              uint32_t s_u32) {
    const uint4* src = (const uint4*)(g + (size_t)rowblk * 128 * 128);
    int tid = threadIdx.x;
#pragma unroll
    for (int q = 0; q < 8; q++) {
        int idx = q * 256 + tid;
        int r = idx >> 4, c = idx & 15;
        cpa16(s_u32 + r * TP2 + c * 16, src + idx);
    }
}

// ---------------- unified bf16-split HMMA GEMM (128x128, fused passes) -------
__global__ void __launch_bounds__(256, 1)
k_gemm_tc(const __nv_bfloat16* __restrict__ Ah, const __nv_bfloat16* __restrict__ Al,
          const __nv_bfloat16* __restrict__ Bh, const __nv_bfloat16* __restrict__ Bl,
          int K, int Ncols,
          float* __restrict__ Cout,
          int head,
          float* __restrict__ muF, float* __restrict__ lvF,
          const float* __restrict__ bmu, const float* __restrict__ blv,
          __nv_bfloat16* __restrict__ ph, __nv_bfloat16* __restrict__ pl)
{
    extern __shared__ __align__(16) char smem[];
    uint32_t sb = smem_u32(smem);
    // stage layout: [Ah Al Bh Bl] x STILE_B, 2 stages

    int tid = threadIdx.x, wid = tid >> 5, lane = tid & 31;
    int m_w = (wid & 3) * 32, n_w = (wid >> 2) * 64;
    int bm = blockIdx.y * 128, bn = blockIdx.x * 128;

    float d[2][8][4];
#pragma unroll
    for (int mi = 0; mi < 2; mi++)
#pragma unroll
        for (int ni = 0; ni < 8; ni++)
#pragma unroll
            for (int q = 0; q < 4; q++) d[mi][ni][q] = 0.f;

    int nsub = K >> 6;
    load_sub(Ah, bm, K, 0, sb);
    load_sub(Al, bm, K, 0, sb + STILE_B);
    load_sub(Bh, bn, K, 0, sb + 2 * STILE_B);
    load_sub(Bl, bn, K, 0, sb + 3 * STILE_B);
    CP_COMMIT();

    for (int s = 0; s < nsub; s++) {
        int cur = s & 1, nxt = cur ^ 1;
        if (s + 1 < nsub) {
            int kc = (s + 1) << 6;
            uint32_t st = sb + nxt * STAGE_B;
            load_sub(Ah, bm, K, kc, st);
            load_sub(Al, bm, K, kc, st + STILE_B);
            load_sub(Bh, bn, K, kc, st + 2 * STILE_B);
            load_sub(Bl, bn, K, kc, st + 3 * STILE_B);
            CP_COMMIT();
            CP_WAIT1();
        } else {
            CP_WAIT0();
        }
        __syncthreads();
        uint32_t st = sb + cur * STAGE_B;
        mma_fused_g(st, st + STILE_B, st + 2 * STILE_B, st + 3 * STILE_B,
                    m_w, n_w, d, lane);
        __syncthreads();
    }

    int g4 = lane >> 2, tq = lane & 3;
    if (!head) {
#pragma unroll
        for (int mi = 0; mi < 2; mi++) {
            int r0 = bm + m_w + mi * 16 + g4;
#pragma unroll
            for (int ni = 0; ni < 8; ni++) {
                int c = bn + n_w + ni * 8 + tq * 2;
                *(float2*)&Cout[(size_t)r0 * Ncols + c]       = make_float2(d[mi][ni][0], d[mi][ni][1]);
                *(float2*)&Cout[(size_t)(r0 + 8) * Ncols + c] = make_float2(d[mi][ni][2], d[mi][ni][3]);
            }
        }
    } else {
        bool is_mu = (blockIdx.x == 0);
        float* F = is_mu ? muF : lvF;
        const float* bias = is_mu ? bmu : blv;
#pragma unroll
        for (int mi = 0; mi < 2; mi++) {
            int r0 = bm + m_w + mi * 16 + g4;
#pragma unroll
            for (int ni = 0; ni < 8; ni++) {
                int c = n_w + ni * 8 + tq * 2;
                float b0 = bias[c], b1 = bias[c + 1];
                float v00 = d[mi][ni][0] + b0, v01 = d[mi][ni][1] + b1;
                float v10 = d[mi][ni][2] + b0, v11 = d[mi][ni][3] + b1;
                *(float2*)&F[(size_t)r0 * LATD + c]       = make_float2(v00, v01);
                *(float2*)&F[(size_t)(r0 + 8) * LATD + c] = make_float2(v10, v11);
                if (is_mu) {
                    __nv_bfloat16 h0, h1, h2, h3, l0, l1, l2, l3;
                    split1(v00, h0, l0); split1(v01, h1, l1);
                    split1(v10, h2, l2); split1(v11, h3, l3);
                    uint32_t hv0 = ((uint32_t)__bfloat16_as_ushort(h1) << 16) | __bfloat16_as_ushort(h0);
                    uint32_t hv1 = ((uint32_t)__bfloat16_as_ushort(h3) << 16) | __bfloat16_as_ushort(h2);
                    uint32_t lv0 = ((uint32_t)__bfloat16_as_ushort(l1) << 16) | __bfloat16_as_ushort(l0);
                    uint32_t lv1 = ((uint32_t)__bfloat16_as_ushort(l3) << 16) | __bfloat16_as_ushort(l2);
                    *(uint32_t*)&ph[(size_t)r0 * LATD + c]       = hv0;
                    *(uint32_t*)&ph[(size_t)(r0 + 8) * LATD + c] = hv1;
                    *(uint32_t*)&pl[(size_t)r0 * LATD + c]       = lv0;
                    *(uint32_t*)&pl[(size_t)(r0 + 8) * LATD + c] = lv1;
                }
            }
        }
    }
}

// ---------------- adj = sigmoid(mu @ mu^T), cp.async-overlapped --------------
__global__ void __launch_bounds__(256, 2)
k_adj_mma(const __nv_bfloat16* __restrict__ Ah, const __nv_bfloat16* __restrict__ Al,
          float* __restrict__ C)
{
    extern __shared__ __align__(16) char smem[];
    char* sA  = smem;
    char* sBh = smem + TILE_B;
    char* sBl = smem + 2 * TILE_B;
    uint32_t uA = smem_u32(sA), uBh = smem_u32(sBh), uBl = smem_u32(sBl);

    int tid = threadIdx.x, wid = tid >> 5, lane = tid & 31;
    int m_w = (wid & 3) * 32, n_w = (wid >> 2) * 64;

    int t = blockIdx.x, bi = 0;
    while (t >= 64 - bi) { t -= 64 - bi; bi++; }
    int bj = bi + t;

    float d[2][8][4];
#pragma unroll
    for (int mi = 0; mi < 2; mi++)
#pragma unroll
        for (int ni = 0; ni < 8; ni++)
#pragma unroll
            for (int q = 0; q < 4; q++) d[mi][ni][q] = 0.f;

    load_tile_cpa(Ah, bi, uA);
    load_tile_cpa(Ah, bj, uBh);
    load_tile_cpa(Al, bj, uBl);
    CP_COMMIT();
    CP_WAIT0();
    __syncthreads();

    mma_pass_adj(uA, uBl, m_w, n_w, d, lane);
    __syncthreads();
    load_tile_cpa(Al, bi, uBl);
    CP_COMMIT();
    mma_pass_adj(uA, uBh, m_w, n_w, d, lane);
    CP_WAIT0();
    __syncthreads();
    mma_pass_adj(uBl, uBh, m_w, n_w, d, lane);

#pragma unroll
    for (int mi = 0; mi < 2; mi++)
#pragma unroll
        for (int ni = 0; ni < 8; ni++)
#pragma unroll
            for (int q = 0; q < 4; q++)
                d[mi][ni][q] = 1.f / (1.f + __expf(-d[mi][ni][q]));

    int g4 = lane >> 2, tq = lane & 3;

#pragma unroll
    for (int mi = 0; mi < 2; mi++) {
        size_t r0 = (size_t)(bi * 128 + m_w + mi * 16 + g4);
#pragma unroll
        for (int ni = 0; ni < 8; ni++) {
            size_t cc = (size_t)(bj * 128 + n_w + ni * 8 + tq * 2);
            *(float2*)&C[r0 * NN + cc]       = make_float2(d[mi][ni][0], d[mi][ni][1]);
            *(float2*)&C[(r0 + 8) * NN + cc] = make_float2(d[mi][ni][2], d[mi][ni][3]);
        }
    }

    if (bi != bj) {
        __syncthreads();
        float* T = (float*)smem;
#pragma unroll
        for (int mi = 0; mi < 2; mi++) {
            int r = m_w + mi * 16 + g4;
#pragma unroll
            for (int ni = 0; ni < 8; ni++) {
                int c = n_w + ni * 8 + tq * 2;
                T[r * 129 + c]           = d[mi][ni][0];
                T[r * 129 + c + 1]       = d[mi][ni][1];
                T[(r + 8) * 129 + c]     = d[mi][ni][2];
                T[(r + 8) * 129 + c + 1] = d[mi][ni][3];
            }
        }
        __syncthreads();
#pragma unroll
        for (int q = 0; q < 64; q++) {
            int lin = q * 256 + tid;
            int cc = lin >> 7, rr = lin & 127;
            C[(size_t)(bj * 128 + cc) * NN + bi * 128 + rr] = T[rr * 129 + cc];
        }
    }
}

// ---------------- launch ----------------------------------------------------
extern "C" void kernel_launch(void* const* d_in, const int* in_sizes, int n_in,
                              void* d_out, int out_size)
{
    const float* x   = (const float*)d_in[0];
    const int*   ei  = (const int*)d_in[1];
    const float* W1  = (const float*)d_in[2];
    const float* b1  = (const float*)d_in[3];
    const float* W2  = (const float*)d_in[4];
    const float* b2  = (const float*)d_in[5];
    const float* Wmu = (const float*)d_in[6];
    const float* bmu = (const float*)d_in[7];
    const float* Wlv = (const float*)d_in[8];
    const float* blv = (const float*)d_in[9];

    float* out = (float*)d_out;
    float* mu  = out + (size_t)NN * NN;
    float* lv  = mu + (size_t)NN * LATD;

    float *p_hs1, *p_hs2;
    __nv_bfloat16 *p_xh, *p_xl, *p_z1h, *p_z1l, *p_z2h, *p_z2l, *p_muh, *p_mul;
    __nv_bfloat16 *p_w1h, *p_w1l, *p_w2h, *p_w2l, *p_whh, *p_whl;
    cudaGetSymbolAddress((void**)&p_hs1, g_hs1);
    cudaGetSymbolAddress((void**)&p_hs2, g_hs2);
    cudaGetSymbolAddress((void**)&p_xh,  g_xh);
    cudaGetSymbolAddress((void**)&p_xl,  g_xl);
    cudaGetSymbolAddress((void**)&p_z1h, g_z1h);
    cudaGetSymbolAddress((void**)&p_z1l, g_z1l);
    cudaGetSymbolAddress((void**)&p_z2h, g_z2h);
    cudaGetSymbolAddress((void**)&p_z2l, g_z2l);
    cudaGetSymbolAddress((void**)&p_muh, g_muh);
    cudaGetSymbolAddress((void**)&p_mul, g_mul);
    cudaGetSymbolAddress((void**)&p_w1h, g_w1h);
    cudaGetSymbolAddress((void**)&p_w1l, g_w1l);
    cudaGetSymbolAddress((void**)&p_w2h, g_w2h);
    cudaGetSymbolAddress((void**)&p_w2l, g_w2l);
    cudaGetSymbolAddress((void**)&p_whh, g_whh);
    cudaGetSymbolAddress((void**)&p_whl, g_whl);

    cudaFuncSetAttribute(k_adj_mma, cudaFuncAttributeMaxDynamicSharedMemorySize, ADJ_SMEM);
    cudaFuncSetAttribute(k_gemm_tc, cudaFuncAttributeMaxDynamicSharedMemorySize, GEMM_SMEM);

    // 1-3: init, detect+prep, count  (GEMM1 stays launch #4 for ncu)
    k_init   <<<8, 1024>>>();
    k_detprep<<<4896, 256>>>(ei, x, W1, W2, Wmu, Wlv);
    k_count  <<<EE / 256, 256>>>(ei);

    // 4: layer-1 GEMM
    k_gemm_tc<<<dim3(H1D / 128, NN / 128), 256, GEMM_SMEM>>>(
        p_xh, p_xl, p_w1h, p_w1l, DIN, H1D, p_hs1, 0,
        nullptr, nullptr, nullptr, nullptr, nullptr, nullptr);

    // 5-8: scan + CSR fill
    k_scan_a<<<32, 256>>>();
    k_scan_b<<<1, 32>>>();
    k_scan_c<<<32, 256>>>();
    k_fill  <<<EE / 256, 256>>>(ei);

    // 9: agg1 -> z1 planes (relu)
    k_agg<<<NN, H1D>>>(p_hs1, b1, p_z1h, p_z1l, H1D, 1);

    // 10-11: layer-2 GEMM + agg2
    k_gemm_tc<<<dim3(LATD / 128, NN / 128), 256, GEMM_SMEM>>>(
        p_z1h, p_z1l, p_w2h, p_w2l, H1D, LATD, p_hs2, 0,
        nullptr, nullptr, nullptr, nullptr, nullptr, nullptr);
    k_agg<<<NN, LATD>>>(p_hs2, b2, p_z2h, p_z2l, LATD, 0);

    // 12: fused heads
    k_gemm_tc<<<dim3(2, NN / 128), 256, GEMM_SMEM>>>(
        p_z2h, p_z2l, p_whh, p_whl, LATD, 2 * LATD, nullptr, 1,
        mu, lv, bmu, blv, p_muh, p_mul);

    // 13: adj = sigmoid(mu @ mu^T)
    k_adj_mma<<<2080, 256, ADJ_SMEM>>>(p_muh, p_mul, out);
}

// round 17
// speedup vs baseline: 1.0001x; 1.0001x over previous
#include <cuda_runtime.h>
#include <cuda_bf16.h>
#include <math.h>
#include <stdint.h>

#define NN   8192
#define EE   262144
#define DIN  512
#define H1D  256
#define LATD 128

// ---------------- scratch (device globals; no allocation allowed) ----------
__device__ int   g_is64;
__device__ int   g_cnt[NN];
__device__ int   g_off[NN + 1];
__device__ int   g_cur[NN];
__device__ int   g_bsum[32];
__device__ int   g_boff[32];
__device__ int   g_csr[EE];
__device__ float g_dis[NN];
__device__ float g_hs1[NN * H1D];
__device__ float g_hs2[NN * LATD];
__device__ __nv_bfloat16 g_xh [NN * DIN],  g_xl [NN * DIN];
__device__ __nv_bfloat16 g_z1h[NN * H1D],  g_z1l[NN * H1D];
__device__ __nv_bfloat16 g_z2h[NN * LATD], g_z2l[NN * LATD];
__device__ __nv_bfloat16 g_muh[NN * LATD], g_mul[NN * LATD];
__device__ __nv_bfloat16 g_w1h[H1D * DIN],  g_w1l[H1D * DIN];
__device__ __nv_bfloat16 g_w2h[LATD * H1D], g_w2l[LATD * H1D];
__device__ __nv_bfloat16 g_whh[2 * LATD * LATD], g_whl[2 * LATD * LATD];

// ---------------- split helpers ---------------------------------------------
__device__ __forceinline__ void split1(float v, __nv_bfloat16& h, __nv_bfloat16& l) {
    h = __float2bfloat16(v);
    l = __float2bfloat16(v - __bfloat162float(h));
}

__device__ __forceinline__ void split4(const float* src, int i,
                                       __nv_bfloat16* ph, __nv_bfloat16* pl) {
    float4 v = ((const float4*)src)[i];
    __nv_bfloat16 h0, h1, h2, h3, l0, l1, l2, l3;
    split1(v.x, h0, l0); split1(v.y, h1, l1); split1(v.z, h2, l2); split1(v.w, h3, l3);
    uint2 hv, lv;
    hv.x = ((uint32_t)__bfloat16_as_ushort(h1) << 16) | __bfloat16_as_ushort(h0);
    hv.y = ((uint32_t)__bfloat16_as_ushort(h3) << 16) | __bfloat16_as_ushort(h2);
    lv.x = ((uint32_t)__bfloat16_as_ushort(l1) << 16) | __bfloat16_as_ushort(l0);
    lv.y = ((uint32_t)__bfloat16_as_ushort(l3) << 16) | __bfloat16_as_ushort(l2);
    ((uint2*)ph)[i] = hv;
    ((uint2*)pl)[i] = lv;
}

__device__ __forceinline__ void wsplit1(const float* W, __nv_bfloat16* outh,
                                        __nv_bfloat16* outl, int Kdim, int Ndim, int idx) {
    int k = idx / Ndim, n = idx % Ndim;
    __nv_bfloat16 h, l;
    split1(W[idx], h, l);
    outh[(size_t)n * Kdim + k] = h;
    outl[(size_t)n * Kdim + k] = l;
}

// ---------------- launch 1 ----------------------------------------------------
__global__ void k_init() {
    int i = blockIdx.x * blockDim.x + threadIdx.x;
    if (i < NN) g_cnt[i] = 0;
    if (i == 0) g_is64 = 1;
}

// ---------------- launch 2: edge-width detect + all operand prep ------------
__global__ void k_detprep(const int* __restrict__ ei, const float* __restrict__ x,
                          const float* __restrict__ W1, const float* __restrict__ W2,
                          const float* __restrict__ Wmu, const float* __restrict__ Wlv) {
    int b = blockIdx.x, t = threadIdx.x;
    if (b < 32) {
        int i = b * 256 + t;
        if (ei[2 * i + 1] != 0) g_is64 = 0;
        return;
    }
    b -= 32;
    if (b < 4096) {
        split4(x, b * 256 + t, g_xh, g_xl);
    } else if (b < 4608) {
        wsplit1(W1, g_w1h, g_w1l, DIN, H1D, (b - 4096) * 256 + t);
    } else if (b < 4736) {
        wsplit1(W2, g_w2h, g_w2l, H1D, LATD, (b - 4608) * 256 + t);
    } else if (b < 4800) {
        wsplit1(Wmu, g_whh, g_whl, LATD, LATD, (b - 4736) * 256 + t);
    } else {
        wsplit1(Wlv, g_whh + LATD * LATD, g_whl + LATD * LATD, LATD, LATD,
                (b - 4800) * 256 + t);
    }
}

__device__ __forceinline__ int edge_val(const int* ei, int idx) {
    return g_is64 ? ei[2 * idx] : ei[idx];
}

// ---------------- launch 3: degree count ------------------------------------
__global__ void k_count(const int* __restrict__ ei) {
    int e = blockIdx.x * blockDim.x + threadIdx.x;
    if (e >= EE) return;
    int c = edge_val(ei, EE + e);
    atomicAdd(&g_cnt[c], 1);
}

// ---------------- hierarchical scan ------------------------------------------
__global__ void k_scan_a() {
    __shared__ int ws[8];
    int t = threadIdx.x, lane = t & 31, w = t >> 5;
    int i = blockIdx.x * 256 + t;
    int c = g_cnt[i];
    int v = c;
#pragma unroll
    for (int d = 1; d < 32; d <<= 1) {
        int u = __shfl_up_sync(0xffffffff, v, d);
        if (lane >= d) v += u;
    }
    if (lane == 31) ws[w] = v;
    __syncthreads();
    if (t < 8) {
        int x = ws[t];
#pragma unroll
        for (int d = 1; d < 8; d <<= 1) {
            int u = __shfl_up_sync(0xff, x, d);
            if (t >= d) x += u;
        }
        ws[t] = x;
    }
    __syncthreads();
    int excl = (w ? ws[w - 1] : 0) + v - c;
    g_off[i] = excl;
    g_dis[i] = rsqrtf((float)(c + 2));
    if (t == 255) g_bsum[blockIdx.x] = excl + c;
}

__global__ void k_scan_b() {
    int t = threadIdx.x;
    int c = g_bsum[t];
    int v = c;
#pragma unroll
    for (int d = 1; d < 32; d <<= 1) {
        int u = __shfl_up_sync(0xffffffff, v, d);
        if (t >= d) v += u;
    }
    g_boff[t] = v - c;
    if (t == 31) g_off[NN] = v;
}

__global__ void k_scan_c() {
    int i = blockIdx.x * 256 + threadIdx.x;
    int o = g_off[i] + g_boff[blockIdx.x];
    g_off[i] = o;
    g_cur[i] = o;
}

__global__ void k_fill(const int* __restrict__ ei) {
    int e = blockIdx.x * blockDim.x + threadIdx.x;
    if (e >= EE) return;
    int r = edge_val(ei, e);
    int c = edge_val(ei, EE + e);
    int p = atomicAdd(&g_cur[c], 1);
    g_csr[p] = r;
}

// ---------------- neighborhood aggregation ----------------------------------
__global__ void k_agg(const float* __restrict__ hs, const float* __restrict__ bias,
                      __nv_bfloat16* __restrict__ zh, __nv_bfloat16* __restrict__ zl,
                      int F, int relu)
{
    __shared__ int   sj[256];
    __shared__ float sd[256];
    int i = blockIdx.x;
    int f = threadIdx.x;
    float di = g_dis[i];
    float a0 = 2.f * di * hs[(size_t)i * F + f], a1 = 0.f, a2 = 0.f, a3 = 0.f;
    int s = g_off[i], e = g_off[i + 1];
    for (int base = s; base < e; base += blockDim.x) {
        int m = min((int)blockDim.x, e - base);
        __syncthreads();
        if (f < m) {
            int j = g_csr[base + f];
            sj[f] = j;
            sd[f] = g_dis[j];
        }
        __syncthreads();
        int p = 0;
        for (; p + 4 <= m; p += 4) {
            float v0 = hs[(size_t)sj[p + 0] * F + f];
            float v1 = hs[(size_t)sj[p + 1] * F + f];
            float v2 = hs[(size_t)sj[p + 2] * F + f];
            float v3 = hs[(size_t)sj[p + 3] * F + f];
            a0 = fmaf(sd[p + 0], v0, a0);
            a1 = fmaf(sd[p + 1], v1, a1);
            a2 = fmaf(sd[p + 2], v2, a2);
            a3 = fmaf(sd[p + 3], v3, a3);
        }
        for (; p < m; p++) a0 = fmaf(sd[p], hs[(size_t)sj[p] * F + f], a0);
    }
    float v = di * ((a0 + a1) + (a2 + a3)) + bias[f];
    if (relu) v = fmaxf(v, 0.f);
    __nv_bfloat16 h, l;
    split1(v, h, l);
    zh[(size_t)i * F + f] = h;
    zl[(size_t)i * F + f] = l;
}

// ---------------- mma.sync helpers ------------------------------------------
__device__ __forceinline__ uint32_t smem_u32(const void* p) {
    uint32_t a;
    asm("{ .reg .u64 t; cvta.to.shared.u64 t, %1; cvt.u32.u64 %0, t; }" : "=r"(a) : "l"(p));
    return a;
}

__device__ __forceinline__ void ldsm_x4(uint32_t* r, uint32_t addr) {
    asm volatile("ldmatrix.sync.aligned.m8n8.x4.shared.b16 {%0,%1,%2,%3}, [%4];"
                 : "=r"(r[0]), "=r"(r[1]), "=r"(r[2]), "=r"(r[3]) : "r"(addr));
}

__device__ __forceinline__ void mma16816(float* d, const uint32_t* a, const uint32_t* b) {
    asm volatile("mma.sync.aligned.m16n8k16.row.col.f32.bf16.bf16.f32 "
                 "{%0,%1,%2,%3}, {%4,%5,%6,%7}, {%8,%9}, {%0,%1,%2,%3};"
                 : "+f"(d[0]), "+f"(d[1]), "+f"(d[2]), "+f"(d[3])
                 : "r"(a[0]), "r"(a[1]), "r"(a[2]), "r"(a[3]), "r"(b[0]), "r"(b[1]));
}

__device__ __forceinline__ void cpa16(uint32_t saddr, const void* g) {
    asm volatile("cp.async.cg.shared.global [%0], [%1], 16;"
                 :: "r"(saddr), "l"(g) : "memory");
}
#define CP_COMMIT() asm volatile("cp.async.commit_group;" ::: "memory")
#define CP_WAIT0()  asm volatile("cp.async.wait_group 0;" ::: "memory")
#define CP_WAIT1()  asm volatile("cp.async.wait_group 1;" ::: "memory")

#define TP        136                     // adj tile pitch (bf16)
#define TP2       (TP * 2)
#define TILE_B    (128 * TP2)             // 34816
#define ADJ_SMEM  (3 * TILE_B)            // 104448 (occ 2)

#define SP        72                      // gemm sub-tile pitch (bf16), 144B rows
#define SPB       (SP * 2)
#define STILE_B   (128 * SPB)             // 18432 (128 rows x 64 cols)
#define STAGE_B   (4 * STILE_B)           // 73728
#define GEMM_SMEM (2 * STAGE_B)           // 147456 (occ 1)

// ---- adj warp pass: 32(m) x 64(n), 8 k-steps, pitch TP ----------------------
__device__ __forceinline__ void mma_pass_adj(uint32_t sA, uint32_t sB, int m_w, int n_w,
                                             float d[2][8][4], int lane) {
    uint32_t a_base = sA + ((m_w + (lane & 15)) * TP + (lane >> 4) * 8) * 2;
    int bmi = lane >> 3;
    uint32_t b_base = sB + ((n_w + ((bmi >> 1) * 8) + (lane & 7)) * TP + (bmi & 1) * 8) * 2;
#pragma unroll
    for (int kk = 0; kk < 8; kk++) {
        int k0 = kk * 16;
        uint32_t a[2][4];
        ldsm_x4(a[0], a_base + k0 * 2);
        ldsm_x4(a[1], a_base + (16 * TP + k0) * 2);
        uint32_t b[4][4];
#pragma unroll
        for (int np = 0; np < 4; np++)
            ldsm_x4(b[np], b_base + (np * 16 * TP + k0) * 2);
#pragma unroll
        for (int mi = 0; mi < 2; mi++)
#pragma unroll
            for (int np = 0; np < 4; np++) {
                mma16816(d[mi][np * 2 + 0], a[mi], &b[np][0]);
                mma16816(d[mi][np * 2 + 1], a[mi], &b[np][2]);
            }
    }
}

// ---- fused gemm k-loop: 32(m) x 64(n), 4 k-steps, all 3 split-passes --------
// fragments loaded ONCE per k-step (12 ldsm / 48 HMMA); HMMA issued in three
// full sweeps over all 16 accumulators so each accumulator's reuse distance is
// 16 instructions (covers HMMA latency) instead of 2.
__device__ __forceinline__ void mma_fused_g(uint32_t uAh, uint32_t uAl,
                                            uint32_t uBh, uint32_t uBl,
                                            int m_w, int n_w, float d[2][8][4], int lane) {
    uint32_t a_off = ((m_w + (lane & 15)) * SP + (lane >> 4) * 8) * 2;
    int bmi = lane >> 3;
    uint32_t b_off = ((n_w + ((bmi >> 1) * 8) + (lane & 7)) * SP + (bmi & 1) * 8) * 2;
#pragma unroll
    for (int kk = 0; kk < 4; kk++) {
        uint32_t k0 = kk * 32;            // 16 bf16 = 32 bytes
        uint32_t ah[2][4], al[2][4], bh[4][4], bl[4][4];
        ldsm_x4(ah[0], uAh + a_off + k0);
        ldsm_x4(ah[1], uAh + a_off + 16 * SPB + k0);
        ldsm_x4(al[0], uAl + a_off + k0);
        ldsm_x4(al[1], uAl + a_off + 16 * SPB + k0);
#pragma unroll
        for (int np = 0; np < 4; np++) {
            ldsm_x4(bh[np], uBh + b_off + np * 16 * SPB + k0);
            ldsm_x4(bl[np], uBl + b_off + np * 16 * SPB + k0);
        }
        // sweep 1: Ah x Bh over all 16 accumulators
#pragma unroll
        for (int mi = 0; mi < 2; mi++)
#pragma unroll
            for (int np = 0; np < 4; np++) {
                mma16816(d[mi][np * 2 + 0], ah[mi], &bh[np][0]);
                mma16816(d[mi][np * 2 + 1], ah[mi], &bh[np][2]);
            }
        // sweep 2: Ah x Bl
#pragma unroll
        for (int mi = 0; mi < 2; mi++)
#pragma unroll
            for (int np = 0; np < 4; np++) {
                mma16816(d[mi][np * 2 + 0], ah[mi], &bl[np][0]);
                mma16816(d[mi][np * 2 + 1], ah[mi], &bl[np][2]);
            }
        // sweep 3: Al x Bh
#pragma unroll
        for (int mi = 0; mi < 2; mi++)
#pragma unroll
            for (int np = 0; np < 4; np++) {
                mma16816(d[mi][np * 2 + 0], al[mi], &bh[np][0]);
                mma16816(d[mi][np * 2 + 1], al[mi], &bh[np][2]);
            }
    }
}

// cp.async 128-row x 64-col bf16 sub-tile (row length K, col offset kc)
__device__ __forceinline__ void load_sub(const __nv_bfloat16* g, int row0, int K,
                                         int kc, uint32_t dst) {
    int tid = threadIdx.x;
#pragma unroll
    for (int q = 0; q < 4; q++) {
        int idx = q * 256 + tid;          // 128 rows x 8 16B-chunks
        int r = idx >> 3, c = idx & 7;
        cpa16(dst + r * SPB + c * 16, g + (size_t)(row0 + r) * K + kc + c * 8);
    }
}

// cp.async 128x128 bf16 tile (contiguous rows, pitch TP) — adj
__device__ __forceinline__ void load_tile_cpa(const __nv_bfloat16* g, int rowblk,
                                              uint32_t s_u32) {
    const uint4* src = (const uint4*)(g + (size_t)rowblk * 128 * 128);
    int tid = threadIdx.x;
#pragma unroll
    for (int q = 0; q < 8; q++) {
        int idx = q * 256 + tid;
        int r = idx >> 4, c = idx & 15;
        cpa16(s_u32 + r * TP2 + c * 16, src + idx);
    }
}

// ---------------- unified bf16-split HMMA GEMM (128x128, fused passes) -------
__global__ void __launch_bounds__(256, 1)
k_gemm_tc(const __nv_bfloat16* __restrict__ Ah, const __nv_bfloat16* __restrict__ Al,
          const __nv_bfloat16* __restrict__ Bh, const __nv_bfloat16* __restrict__ Bl,
          int K, int Ncols,
          float* __restrict__ Cout,
          int head,
          float* __restrict__ muF, float* __restrict__ lvF,
          const float* __restrict__ bmu, const float* __restrict__ blv,
          __nv_bfloat16* __restrict__ ph, __nv_bfloat16* __restrict__ pl)
{
    extern __shared__ __align__(16) char smem[];
    uint32_t sb = smem_u32(smem);
    // stage layout: [Ah Al Bh Bl] x STILE_B, 2 stages

    int tid = threadIdx.x, wid = tid >> 5, lane = tid & 31;
    int m_w = (wid & 3) * 32, n_w = (wid >> 2) * 64;
    int bm = blockIdx.y * 128, bn = blockIdx.x * 128;

    float d[2][8][4];
#pragma unroll
    for (int mi = 0; mi < 2; mi++)
#pragma unroll
        for (int ni = 0; ni < 8; ni++)
#pragma unroll
            for (int q = 0; q < 4; q++) d[mi][ni][q] = 0.f;

    int nsub = K >> 6;
    load_sub(Ah, bm, K, 0, sb);
    load_sub(Al, bm, K, 0, sb + STILE_B);
    load_sub(Bh, bn, K, 0, sb + 2 * STILE_B);
    load_sub(Bl, bn, K, 0, sb + 3 * STILE_B);
    CP_COMMIT();

    for (int s = 0; s < nsub; s++) {
        int cur = s & 1, nxt = cur ^ 1;
        if (s + 1 < nsub) {
            int kc = (s + 1) << 6;
            uint32_t st = sb + nxt * STAGE_B;
            load_sub(Ah, bm, K, kc, st);
            load_sub(Al, bm, K, kc, st + STILE_B);
            load_sub(Bh, bn, K, kc, st + 2 * STILE_B);
            load_sub(Bl, bn, K, kc, st + 3 * STILE_B);
            CP_COMMIT();
            CP_WAIT1();
        } else {
            CP_WAIT0();
        }
        __syncthreads();
        uint32_t st = sb + cur * STAGE_B;
        mma_fused_g(st, st + STILE_B, st + 2 * STILE_B, st + 3 * STILE_B,
                    m_w, n_w, d, lane);
        __syncthreads();
    }

    int g4 = lane >> 2, tq = lane & 3;
    if (!head) {
#pragma unroll
        for (int mi = 0; mi < 2; mi++) {
            int r0 = bm + m_w + mi * 16 + g4;
#pragma unroll
            for (int ni = 0; ni < 8; ni++) {
                int c = bn + n_w + ni * 8 + tq * 2;
                *(float2*)&Cout[(size_t)r0 * Ncols + c]       = make_float2(d[mi][ni][0], d[mi][ni][1]);
                *(float2*)&Cout[(size_t)(r0 + 8) * Ncols + c] = make_float2(d[mi][ni][2], d[mi][ni][3]);
            }
        }
    } else {
        bool is_mu = (blockIdx.x == 0);
        float* F = is_mu ? muF : lvF;
        const float* bias = is_mu ? bmu : blv;
#pragma unroll
        for (int mi = 0; mi < 2; mi++) {
            int r0 = bm + m_w + mi * 16 + g4;
#pragma unroll
            for (int ni = 0; ni < 8; ni++) {
                int c = n_w + ni * 8 + tq * 2;
                float b0 = bias[c], b1 = bias[c + 1];
                float v00 = d[mi][ni][0] + b0, v01 = d[mi][ni][1] + b1;
                float v10 = d[mi][ni][2] + b0, v11 = d[mi][ni][3] + b1;
                *(float2*)&F[(size_t)r0 * LATD + c]       = make_float2(v00, v01);
                *(float2*)&F[(size_t)(r0 + 8) * LATD + c] = make_float2(v10, v11);
                if (is_mu) {
                    __nv_bfloat16 h0, h1, h2, h3, l0, l1, l2, l3;
                    split1(v00, h0, l0); split1(v01, h1, l1);
                    split1(v10, h2, l2); split1(v11, h3, l3);
                    uint32_t hv0 = ((uint32_t)__bfloat16_as_ushort(h1) << 16) | __bfloat16_as_ushort(h0);
                    uint32_t hv1 = ((uint32_t)__bfloat16_as_ushort(h3) << 16) | __bfloat16_as_ushort(h2);
                    uint32_t lv0 = ((uint32_t)__bfloat16_as_ushort(l1) << 16) | __bfloat16_as_ushort(l0);
                    uint32_t lv1 = ((uint32_t)__bfloat16_as_ushort(l3) << 16) | __bfloat16_as_ushort(l2);
                    *(uint32_t*)&ph[(size_t)r0 * LATD + c]       = hv0;
                    *(uint32_t*)&ph[(size_t)(r0 + 8) * LATD + c] = hv1;
                    *(uint32_t*)&pl[(size_t)r0 * LATD + c]       = lv0;
                    *(uint32_t*)&pl[(size_t)(r0 + 8) * LATD + c] = lv1;
                }
            }
        }
    }
}

// ---------------- adj = sigmoid(mu @ mu^T), cp.async-overlapped --------------
__global__ void __launch_bounds__(256, 2)
k_adj_mma(const __nv_bfloat16* __restrict__ Ah, const __nv_bfloat16* __restrict__ Al,
          float* __restrict__ C)
{
    extern __shared__ __align__(16) char smem[];
    char* sA  = smem;
    char* sBh = smem + TILE_B;
    char* sBl = smem + 2 * TILE_B;
    uint32_t uA = smem_u32(sA), uBh = smem_u32(sBh), uBl = smem_u32(sBl);

    int tid = threadIdx.x, wid = tid >> 5, lane = tid & 31;
    int m_w = (wid & 3) * 32, n_w = (wid >> 2) * 64;

    int t = blockIdx.x, bi = 0;
    while (t >= 64 - bi) { t -= 64 - bi; bi++; }
    int bj = bi + t;

    float d[2][8][4];
#pragma unroll
    for (int mi = 0; mi < 2; mi++)
#pragma unroll
        for (int ni = 0; ni < 8; ni++)
#pragma unroll
            for (int q = 0; q < 4; q++) d[mi][ni][q] = 0.f;

    load_tile_cpa(Ah, bi, uA);
    load_tile_cpa(Ah, bj, uBh);
    load_tile_cpa(Al, bj, uBl);
    CP_COMMIT();
    CP_WAIT0();
    __syncthreads();

    mma_pass_adj(uA, uBl, m_w, n_w, d, lane);
    __syncthreads();
    load_tile_cpa(Al, bi, uBl);
    CP_COMMIT();
    mma_pass_adj(uA, uBh, m_w, n_w, d, lane);
    CP_WAIT0();
    __syncthreads();
    mma_pass_adj(uBl, uBh, m_w, n_w, d, lane);

#pragma unroll
    for (int mi = 0; mi < 2; mi++)
#pragma unroll
        for (int ni = 0; ni < 8; ni++)
#pragma unroll
            for (int q = 0; q < 4; q++)
                d[mi][ni][q] = 1.f / (1.f + __expf(-d[mi][ni][q]));

    int g4 = lane >> 2, tq = lane & 3;

#pragma unroll
    for (int mi = 0; mi < 2; mi++) {
        size_t r0 = (size_t)(bi * 128 + m_w + mi * 16 + g4);
#pragma unroll
        for (int ni = 0; ni < 8; ni++) {
            size_t cc = (size_t)(bj * 128 + n_w + ni * 8 + tq * 2);
            *(float2*)&C[r0 * NN + cc]       = make_float2(d[mi][ni][0], d[mi][ni][1]);
            *(float2*)&C[(r0 + 8) * NN + cc] = make_float2(d[mi][ni][2], d[mi][ni][3]);
        }
    }

    if (bi != bj) {
        __syncthreads();
        float* T = (float*)smem;
#pragma unroll
        for (int mi = 0; mi < 2; mi++) {
            int r = m_w + mi * 16 + g4;
#pragma unroll
            for (int ni = 0; ni < 8; ni++) {
                int c = n_w + ni * 8 + tq * 2;
                T[r * 129 + c]           = d[mi][ni][0];
                T[r * 129 + c + 1]       = d[mi][ni][1];
                T[(r + 8) * 129 + c]     = d[mi][ni][2];
                T[(r + 8) * 129 + c + 1] = d[mi][ni][3];
            }
        }
        __syncthreads();
#pragma unroll
        for (int q = 0; q < 64; q++) {
            int lin = q * 256 + tid;
            int cc = lin >> 7, rr = lin & 127;
            C[(size_t)(bj * 128 + cc) * NN + bi * 128 + rr] = T[rr * 129 + cc];
        }
    }
}

// ---------------- launch ----------------------------------------------------
extern "C" void kernel_launch(void* const* d_in, const int* in_sizes, int n_in,
                              void* d_out, int out_size)
{
    const float* x   = (const float*)d_in[0];
    const int*   ei  = (const int*)d_in[1];
    const float* W1  = (const float*)d_in[2];
    const float* b1  = (const float*)d_in[3];
    const float* W2  = (const float*)d_in[4];
    const float* b2  = (const float*)d_in[5];
    const float* Wmu = (const float*)d_in[6];
    const float* bmu = (const float*)d_in[7];
    const float* Wlv = (const float*)d_in[8];
    const float* blv = (const float*)d_in[9];

    float* out = (float*)d_out;
    float* mu  = out + (size_t)NN * NN;
    float* lv  = mu + (size_t)NN * LATD;

    float *p_hs1, *p_hs2;
    __nv_bfloat16 *p_xh, *p_xl, *p_z1h, *p_z1l, *p_z2h, *p_z2l, *p_muh, *p_mul;
    __nv_bfloat16 *p_w1h, *p_w1l, *p_w2h, *p_w2l, *p_whh, *p_whl;
    cudaGetSymbolAddress((void**)&p_hs1, g_hs1);
    cudaGetSymbolAddress((void**)&p_hs2, g_hs2);
    cudaGetSymbolAddress((void**)&p_xh,  g_xh);
    cudaGetSymbolAddress((void**)&p_xl,  g_xl);
    cudaGetSymbolAddress((void**)&p_z1h, g_z1h);
    cudaGetSymbolAddress((void**)&p_z1l, g_z1l);
    cudaGetSymbolAddress((void**)&p_z2h, g_z2h);
    cudaGetSymbolAddress((void**)&p_z2l, g_z2l);
    cudaGetSymbolAddress((void**)&p_muh, g_muh);
    cudaGetSymbolAddress((void**)&p_mul, g_mul);
    cudaGetSymbolAddress((void**)&p_w1h, g_w1h);
    cudaGetSymbolAddress((void**)&p_w1l, g_w1l);
    cudaGetSymbolAddress((void**)&p_w2h, g_w2h);
    cudaGetSymbolAddress((void**)&p_w2l, g_w2l);
    cudaGetSymbolAddress((void**)&p_whh, g_whh);
    cudaGetSymbolAddress((void**)&p_whl, g_whl);

    cudaFuncSetAttribute(k_adj_mma, cudaFuncAttributeMaxDynamicSharedMemorySize, ADJ_SMEM);
    cudaFuncSetAttribute(k_gemm_tc, cudaFuncAttributeMaxDynamicSharedMemorySize, GEMM_SMEM);

    // 1-3: init, detect+prep, count  (GEMM1 stays launch #4 for ncu)
    k_init   <<<8, 1024>>>();
    k_detprep<<<4896, 256>>>(ei, x, W1, W2, Wmu, Wlv);
    k_count  <<<EE / 256, 256>>>(ei);

    // 4: layer-1 GEMM
    k_gemm_tc<<<dim3(H1D / 128, NN / 128), 256, GEMM_SMEM>>>(
        p_xh, p_xl, p_w1h, p_w1l, DIN, H1D, p_hs1, 0,
        nullptr, nullptr, nullptr, nullptr, nullptr, nullptr);

    // 5-8: scan + CSR fill
    k_scan_a<<<32, 256>>>();
    k_scan_b<<<1, 32>>>();
    k_scan_c<<<32, 256>>>();
    k_fill  <<<EE / 256, 256>>>(ei);

    // 9: agg1 -> z1 planes (relu)
    k_agg<<<NN, H1D>>>(p_hs1, b1, p_z1h, p_z1l, H1D, 1);

    // 10-11: layer-2 GEMM + agg2
    k_gemm_tc<<<dim3(LATD / 128, NN / 128), 256, GEMM_SMEM>>>(
        p_z1h, p_z1l, p_w2h, p_w2l, H1D, LATD, p_hs2, 0,
        nullptr, nullptr, nullptr, nullptr, nullptr, nullptr);
    k_agg<<<NN, LATD>>>(p_hs2, b2, p_z2h, p_z2l, LATD, 0);

    // 12: fused heads
    k_gemm_tc<<<dim3(2, NN / 128), 256, GEMM_SMEM>>>(
        p_z2h, p_z2l, p_whh, p_whl, LATD, 2 * LATD, nullptr, 1,
        mu, lv, bmu, blv, p_muh, p_mul);

    // 13: adj = sigmoid(mu @ mu^T)
    k_adj_mma<<<2080, 256, ADJ_SMEM>>>(p_muh, p_mul, out);
}